// round 1
// baseline (speedup 1.0000x reference)
#include <cuda_runtime.h>

// KalmanFilter: B=128, T=256, V=256, state=4 (x,y,vx,vy), obs=2.
// Decouples exactly into two identical 2-state filters sharing one 2x2 covariance.

#define BQ 128
#define TQ 256
#define VQ 256
#define FSTEP (VQ * 3)   // floats per time step per batch element: 768
#define DCH 16           // time steps per prefetch chunk
#define NCH (TQ / DCH)   // 16 chunks

__global__ void __launch_bounds__(64)
kalman_kernel(const float* __restrict__ batch, float* __restrict__ out)
{
    const int tid = blockIdx.x * 64 + threadIdx.x;   // 0..32767
    const int b = tid >> 8;          // batch index
    const int v = tid & 255;         // track index

    const float* p = batch + ((size_t)b * TQ * VQ + v) * 3;

    // State: two decoupled (pos, vel) filters + shared symmetric 2x2 covariance
    float sx0 = 0.f, sx1 = 0.f, sy0 = 0.f, sy1 = 0.f;
    float p00 = 1000.f, p01 = 0.f, p11 = 1000.f;

    float lA[DCH], xA[DCH], yA[DCH];
    float lB[DCH], xB[DCH], yB[DCH];

    // One Kalman step (branchless; masked step => g = 0 => pure predict)
    auto kstep = [&](float lab, float zx, float zy) {
        // predict: s = F s ; P = F P F^T + Q  (F = [[1,1],[0,1]], Q = 0.01 I)
        sx0 += sx1;
        sy0 += sy1;
        float np01 = p01 + p11;
        p00 = p00 + p01 + np01 + 0.01f;
        p01 = np01;
        p11 += 0.01f;
        // update: S = p00 + 1 (scalar), K = [p00, p01]/S
        float inv = __fdividef(1.0f, p00 + 1.0f);
        float g   = (lab != -1.0f) ? inv : 0.0f;
        float k0 = p00 * g;
        float k1 = p01 * g;
        float rx = zx - sx0;
        float ry = zy - sy0;
        sx0 = fmaf(k0, rx, sx0);
        sx1 = fmaf(k1, rx, sx1);
        sy0 = fmaf(k0, ry, sy0);
        sy1 = fmaf(k1, ry, sy1);
        // P = (I - K H) P  : p11 first (needs old p01)
        p11 = fmaf(-k1, p01, p11);
        p01 = fmaf(-k0, p01, p01);
        p00 = fmaf(-k0, p00, p00);
    };

    // Prefill chunk 0 into A
    #pragma unroll
    for (int i = 0; i < DCH; i++) {
        lA[i] = p[i * FSTEP + 0];
        xA[i] = p[i * FSTEP + 1];
        yA[i] = p[i * FSTEP + 2];
    }

    #pragma unroll 1
    for (int c = 0; c < NCH; c += 2) {
        // prefetch chunk c+1 into B
        const float* pB = p + (size_t)DCH * FSTEP;
        #pragma unroll
        for (int i = 0; i < DCH; i++) {
            lB[i] = pB[i * FSTEP + 0];
            xB[i] = pB[i * FSTEP + 1];
            yB[i] = pB[i * FSTEP + 2];
        }
        // process chunk c
        #pragma unroll
        for (int i = 0; i < DCH; i++) kstep(lA[i], xA[i], yA[i]);

        // prefetch chunk c+2 into A (clamped: last iteration re-reads chunk c, unused)
        const float* pA = (c + 2 < NCH) ? (p + (size_t)2 * DCH * FSTEP) : p;
        #pragma unroll
        for (int i = 0; i < DCH; i++) {
            lA[i] = pA[i * FSTEP + 0];
            xA[i] = pA[i * FSTEP + 1];
            yA[i] = pA[i * FSTEP + 2];
        }
        // process chunk c+1
        #pragma unroll
        for (int i = 0; i < DCH; i++) kstep(lB[i], xB[i], yB[i]);

        p += (size_t)2 * DCH * FSTEP;
    }

    float* o = out + ((size_t)b * VQ + v) * 3;
    o[0] = 1.0f;
    o[1] = sx0;
    o[2] = sy0;
}

extern "C" void kernel_launch(void* const* d_in, const int* in_sizes, int n_in,
                              void* d_out, int out_size)
{
    const float* batch = (const float*)d_in[0];
    float* out = (float*)d_out;
    // 32768 filters, 64 threads/block -> 512 blocks (even spread over 148 SMs)
    kalman_kernel<<<512, 64>>>(batch, out);
}

// round 2
// speedup vs baseline: 1.8582x; 1.8582x over previous
#include <cuda_runtime.h>

// KalmanFilter: B=128, T=256, V=256. Decouples into two identical 2-state
// filters sharing one symmetric 2x2 covariance (Riccati recursion depends
// only on the mask sequence; cross-covariances stay exactly zero).
//
// Memory engine: cp.async (LDGSTS) 3-stage smem ring, 1 warp per block.

#define TQ 256
#define VQ 256
#define FSTEP (VQ * 3)            // floats per timestep per batch elem: 768
#define DCH 16                    // timesteps per chunk
#define NCH (TQ / DCH)            // 16 chunks
#define STAGES 3
#define TPB 32                    // one warp per block
#define TRACKS 32                 // tracks (v) per block
#define FLT_PER_STEP (TRACKS * 3)         // 96 floats per step per block
#define F4_PER_STEP  (FLT_PER_STEP / 4)   // 24 float4
#define F4_PER_CHUNK (DCH * F4_PER_STEP)  // 384 float4 = 6144 B
#define F4_PER_THR   (F4_PER_CHUNK / TPB) // 12 cp.async per thread per chunk

__global__ void __launch_bounds__(TPB)
kalman_kernel(const float* __restrict__ batch, float* __restrict__ out)
{
    __shared__ float4 buf[STAGES][F4_PER_CHUNK];   // 3 * 6 KB = 18 KB

    const int tid = threadIdx.x;
    const int b   = blockIdx.x >> 3;               // 8 blocks per batch elem
    const int v0  = (blockIdx.x & 7) * TRACKS;
    const char* gbase = (const char*)(batch + ((size_t)b * TQ * VQ + v0) * 3);

    // ---- issue one chunk into stage s via cp.async ----
    auto issue = [&](int chunk, int s) {
        const char* cbase = gbase + (size_t)chunk * DCH * (FSTEP * 4);
        unsigned sbase = (unsigned)__cvta_generic_to_shared(&buf[s][0]);
        #pragma unroll
        for (int k = 0; k < F4_PER_THR; k++) {
            int j    = tid + k * TPB;
            int step = j / F4_PER_STEP;
            int rem  = j - step * F4_PER_STEP;
            const char* g = cbase + step * (FSTEP * 4) + rem * 16;
            unsigned sa   = sbase + (unsigned)j * 16;
            asm volatile("cp.async.cg.shared.global [%0], [%1], 16;\n"
                         :: "r"(sa), "l"(g));
        }
        asm volatile("cp.async.commit_group;\n" ::: "memory");
    };

    // ---- filter state ----
    float sx0 = 0.f, sx1 = 0.f, sy0 = 0.f, sy1 = 0.f;
    float p00 = 1000.f, p01 = 0.f, p11 = 1000.f;

    auto kstep = [&](float lab, float zx, float zy) {
        // predict: F = [[1,1],[0,1]], Q = 0.01 I
        sx0 += sx1;
        sy0 += sy1;
        float np01 = p01 + p11;
        p00 = p00 + p01 + np01 + 0.01f;
        p01 = np01;
        p11 += 0.01f;
        // update: S = p00 + 1 (scalar); masked step => g = 0 => pure predict
        float inv = __fdividef(1.0f, p00 + 1.0f);
        float g   = (lab != -1.0f) ? inv : 0.0f;
        float k0  = p00 * g;
        float k1  = p01 * g;
        float rx  = zx - sx0;
        float ry  = zy - sy0;
        sx0 = fmaf(k0, rx, sx0);
        sx1 = fmaf(k1, rx, sx1);
        sy0 = fmaf(k0, ry, sy0);
        sy1 = fmaf(k1, ry, sy1);
        p11 = fmaf(-k1, p01, p11);   // uses old p01
        p01 = fmaf(-k0, p01, p01);
        p00 = fmaf(-k0, p00, p00);
    };

    // ---- prologue: fill the ring ----
    issue(0, 0);
    issue(1, 1);
    issue(2, 2);

    int stage = 0;
    #pragma unroll 1
    for (int c = 0; c < NCH; c++) {
        // oldest outstanding group (chunk c) must be complete
        asm volatile("cp.async.wait_group %0;\n" :: "n"(STAGES - 1) : "memory");
        __syncwarp();

        const float* sb = (const float*)&buf[stage][0];
        #pragma unroll
        for (int i = 0; i < DCH; i++) {
            float lab = sb[i * FLT_PER_STEP + tid * 3 + 0];
            float zx  = sb[i * FLT_PER_STEP + tid * 3 + 1];
            float zy  = sb[i * FLT_PER_STEP + tid * 3 + 2];
            kstep(lab, zx, zy);
        }
        __syncwarp();

        // refill this stage with chunk c+STAGES (same stage index)
        if (c + STAGES < NCH) issue(c + STAGES, stage);

        stage = (stage + 1 == STAGES) ? 0 : stage + 1;
    }

    float* o = out + ((size_t)b * VQ + v0 + tid) * 3;
    o[0] = 1.0f;
    o[1] = sx0;
    o[2] = sy0;
}

extern "C" void kernel_launch(void* const* d_in, const int* in_sizes, int n_in,
                              void* d_out, int out_size)
{
    const float* batch = (const float*)d_in[0];
    float* out = (float*)d_out;
    // 32768 filters, 32 threads/block -> 1024 blocks (~6.9/SM, balanced)
    kalman_kernel<<<1024, TPB>>>(batch, out);
}